// round 1
// baseline (speedup 1.0000x reference)
#include <cuda_runtime.h>
#include <math.h>

// Problem dims (B=1)
#define LEN   3072
#define HID   3072
#define NH    24
#define HD    128
#define MLPD  12288
#define N1    (3*HID + MLPD)   // 21504  (lin1 out)
#define N2    (HID + MLPD)     // 15360  (lin2 in)
#define EPSF  1e-6f

// ---------------- scratch (static device allocs; no cudaMalloc allowed) ----
__device__ float g_sv[HID];                       // silu(vec)
__device__ float g_mod[3*HID];                    // shift|scale|gate
__device__ float g_xmod[(size_t)LEN*HID];         // modulated LN output
__device__ float g_proj[(size_t)LEN*N1];          // lin1 output (264 MB)
__device__ float g_q[(size_t)NH*LEN*HD];
__device__ float g_k[(size_t)NH*LEN*HD];
__device__ float g_v[(size_t)NH*LEN*HD];
__device__ float g_S[(size_t)NH*LEN*LEN];         // logits / probs (906 MB)
__device__ float g_attn[(size_t)NH*LEN*HD];
__device__ float g_cat[(size_t)LEN*N2];           // [attn | gelu(mlp)] (189 MB)

// ---------------- small elementwise kernels --------------------------------
__global__ void silu_kernel(const float* __restrict__ vec) {
    int i = blockIdx.x * blockDim.x + threadIdx.x;
    if (i < HID) {
        float v = vec[i];
        g_sv[i] = v / (1.f + __expf(-v));
    }
}

// mod[j] = dot(silu(vec), mod_w[j,:]) + mod_b[j]   (one warp per j)
__global__ void gemv_mod_kernel(const float* __restrict__ W, const float* __restrict__ b) {
    int j = blockIdx.x * 8 + (threadIdx.x >> 5);
    int lane = threadIdx.x & 31;
    const float4* w4 = (const float4*)(W + (size_t)j * HID);
    const float4* s4 = (const float4*)g_sv;
    float acc = 0.f;
    for (int i = lane; i < HID/4; i += 32) {
        float4 w = w4[i], s = s4[i];
        acc += w.x*s.x + w.y*s.y + w.z*s.z + w.w*s.w;
    }
    #pragma unroll
    for (int o = 16; o; o >>= 1) acc += __shfl_xor_sync(0xffffffffu, acc, o);
    if (lane == 0) g_mod[j] = acc + b[j];
}

// LayerNorm + modulation: x_mod = LN(x)*(1+scale) + shift. One block per row.
__global__ void layernorm_kernel(const float* __restrict__ x) {
    __shared__ float shA[8], shB[8];
    __shared__ float s_mu, s_r;
    int l = blockIdx.x, t = threadIdx.x;
    const float* row = x + (size_t)l * HID;
    float v[12];
    float s = 0.f, ss = 0.f;
    #pragma unroll
    for (int i = 0; i < 12; i++) {
        v[i] = row[t + i*256];
        s += v[i]; ss += v[i]*v[i];
    }
    #pragma unroll
    for (int o = 16; o; o >>= 1) {
        s  += __shfl_xor_sync(0xffffffffu, s,  o);
        ss += __shfl_xor_sync(0xffffffffu, ss, o);
    }
    if ((t & 31) == 0) { shA[t>>5] = s; shB[t>>5] = ss; }
    __syncthreads();
    if (t == 0) {
        float a = 0.f, bb = 0.f;
        #pragma unroll
        for (int w = 0; w < 8; w++) { a += shA[w]; bb += shB[w]; }
        float mu = a / HID;
        float var = bb / HID - mu*mu;
        s_mu = mu; s_r = rsqrtf(var + EPSF);
    }
    __syncthreads();
    float mu = s_mu, r = s_r;
    float* orow = g_xmod + (size_t)l * HID;
    #pragma unroll
    for (int i = 0; i < 12; i++) {
        int kcol = t + i*256;
        orow[kcol] = (v[i] - mu) * r * (1.f + g_mod[HID + kcol]) + g_mod[kcol];
    }
}

// ---------------- generic 128x128x8 tiled SGEMM ----------------------------
// C[M,N] = alpha * A[M,K] * op(B) + bias;  BT=1: B is [N,K] row-major (NT)
//                                          BT=0: B is [K,N] row-major (NN)
// All of M,N divisible by 128; K divisible by 8; pointers 16B-aligned.
template<int BT>
__global__ void __launch_bounds__(256) gemm_kernel(
    const float* __restrict__ A, const float* __restrict__ B,
    const float* __restrict__ bias, float* __restrict__ C,
    int M, int N, int K, float alpha,
    size_t sA, size_t sB, size_t sC)
{
    __shared__ float As[8][128];
    __shared__ float Bs[8][128];
    A += (size_t)blockIdx.z * sA;
    B += (size_t)blockIdx.z * sB;
    C += (size_t)blockIdx.z * sC;
    int tid = threadIdx.x;
    int m0 = blockIdx.y * 128, n0 = blockIdx.x * 128;
    int tx = tid & 15, ty = tid >> 4;
    int a_m = tid >> 1, a_k = (tid & 1) * 4;

    float acc[8][8];
    #pragma unroll
    for (int i = 0; i < 8; i++)
        #pragma unroll
        for (int j = 0; j < 8; j++) acc[i][j] = 0.f;

    for (int kt = 0; kt < K; kt += 8) {
        float4 av = *(const float4*)(A + (size_t)(m0 + a_m) * K + kt + a_k);
        As[a_k+0][a_m] = av.x; As[a_k+1][a_m] = av.y;
        As[a_k+2][a_m] = av.z; As[a_k+3][a_m] = av.w;
        if (BT) {
            float4 bv = *(const float4*)(B + (size_t)(n0 + a_m) * K + kt + a_k);
            Bs[a_k+0][a_m] = bv.x; Bs[a_k+1][a_m] = bv.y;
            Bs[a_k+2][a_m] = bv.z; Bs[a_k+3][a_m] = bv.w;
        } else {
            int b_k = tid >> 5, b_n = (tid & 31) * 4;
            float4 bv = *(const float4*)(B + (size_t)(kt + b_k) * N + n0 + b_n);
            *(float4*)&Bs[b_k][b_n] = bv;
        }
        __syncthreads();
        #pragma unroll
        for (int kk = 0; kk < 8; kk++) {
            float a[8], b[8];
            *(float4*)(a)     = *(const float4*)&As[kk][ty*8];
            *(float4*)(a + 4) = *(const float4*)&As[kk][ty*8 + 4];
            *(float4*)(b)     = *(const float4*)&Bs[kk][tx*8];
            *(float4*)(b + 4) = *(const float4*)&Bs[kk][tx*8 + 4];
            #pragma unroll
            for (int i = 0; i < 8; i++)
                #pragma unroll
                for (int j = 0; j < 8; j++)
                    acc[i][j] += a[i] * b[j];
        }
        __syncthreads();
    }

    #pragma unroll
    for (int i = 0; i < 8; i++) {
        int row = m0 + ty*8 + i;
        #pragma unroll
        for (int j = 0; j < 8; j += 4) {
            int col = n0 + tx*8 + j;
            float4 o;
            o.x = alpha * acc[i][j+0] + (bias ? bias[col+0] : 0.f);
            o.y = alpha * acc[i][j+1] + (bias ? bias[col+1] : 0.f);
            o.z = alpha * acc[i][j+2] + (bias ? bias[col+2] : 0.f);
            o.w = alpha * acc[i][j+3] + (bias ? bias[col+3] : 0.f);
            *(float4*)(C + (size_t)row * N + col) = o;
        }
    }
}

// ---------------- qkv split + RMS + RoPE -----------------------------------
// one warp per (h,l); lane owns d = lane*4..lane*4+3 (rope pairs stay in-thread)
__global__ void qkv_prep_kernel(const float* __restrict__ pe,
                                const float* __restrict__ q_scale,
                                const float* __restrict__ k_scale) {
    int w = threadIdx.x >> 5, lane = threadIdx.x & 31;
    int r = blockIdx.x * 8 + w;          // 0 .. NH*LEN-1
    int h = r / LEN, l = r % LEN;
    const float* prow = g_proj + (size_t)l * N1;
    float4 q4 = *(const float4*)(prow +            h*HD + lane*4);
    float4 k4 = *(const float4*)(prow +   HID    + h*HD + lane*4);
    float4 v4 = *(const float4*)(prow + 2*HID    + h*HD + lane*4);

    float qs = q4.x*q4.x + q4.y*q4.y + q4.z*q4.z + q4.w*q4.w;
    float ks = k4.x*k4.x + k4.y*k4.y + k4.z*k4.z + k4.w*k4.w;
    #pragma unroll
    for (int o = 16; o; o >>= 1) {
        qs += __shfl_xor_sync(0xffffffffu, qs, o);
        ks += __shfl_xor_sync(0xffffffffu, ks, o);
    }
    float qr = rsqrtf(qs / HD + EPSF);
    float kr = rsqrtf(ks / HD + EPSF);
    float4 qsc = *(const float4*)(q_scale + lane*4);
    float4 ksc = *(const float4*)(k_scale + lane*4);
    float tq[4] = { q4.x*qr*qsc.x, q4.y*qr*qsc.y, q4.z*qr*qsc.z, q4.w*qr*qsc.w };
    float tk[4] = { k4.x*kr*ksc.x, k4.y*kr*ksc.y, k4.z*kr*ksc.z, k4.w*kr*ksc.w };

    // pe layout: [l][i][j][c] -> l*256 + i*4 + j*2 + c;  i = lane*2 + p
    const float* peb = pe + (size_t)l * 256 + lane * 8;
    float4 oq, ok;
    oq.x = peb[0]*tq[0] + peb[1]*tq[1];
    oq.y = peb[2]*tq[0] + peb[3]*tq[1];
    oq.z = peb[4]*tq[2] + peb[5]*tq[3];
    oq.w = peb[6]*tq[2] + peb[7]*tq[3];
    ok.x = peb[0]*tk[0] + peb[1]*tk[1];
    ok.y = peb[2]*tk[0] + peb[3]*tk[1];
    ok.z = peb[4]*tk[2] + peb[5]*tk[3];
    ok.w = peb[6]*tk[2] + peb[7]*tk[3];

    size_t base = ((size_t)h * LEN + l) * HD + lane * 4;
    *(float4*)(g_q + base) = oq;
    *(float4*)(g_k + base) = ok;
    *(float4*)(g_v + base) = v4;
}

// ---------------- softmax over rows of g_S ---------------------------------
__global__ void softmax_kernel() {
    __shared__ float shA[8];
    __shared__ float s_bc;
    size_t row = blockIdx.x;             // h*LEN + q
    float* p = g_S + row * (size_t)LEN;
    int t = threadIdx.x;
    float x[12];
    float mx = -1e30f;
    #pragma unroll
    for (int i = 0; i < 12; i++) { x[i] = p[t + i*256]; mx = fmaxf(mx, x[i]); }
    #pragma unroll
    for (int o = 16; o; o >>= 1) mx = fmaxf(mx, __shfl_xor_sync(0xffffffffu, mx, o));
    if ((t & 31) == 0) shA[t>>5] = mx;
    __syncthreads();
    if (t == 0) {
        float m = shA[0];
        #pragma unroll
        for (int w = 1; w < 8; w++) m = fmaxf(m, shA[w]);
        s_bc = m;
    }
    __syncthreads();
    mx = s_bc;
    float s = 0.f;
    #pragma unroll
    for (int i = 0; i < 12; i++) { x[i] = __expf(x[i] - mx); s += x[i]; }
    #pragma unroll
    for (int o = 16; o; o >>= 1) s += __shfl_xor_sync(0xffffffffu, s, o);
    __syncthreads();
    if ((t & 31) == 0) shA[t>>5] = s;
    __syncthreads();
    if (t == 0) {
        float a = 0.f;
        #pragma unroll
        for (int w = 0; w < 8; w++) a += shA[w];
        s_bc = 1.f / a;
    }
    __syncthreads();
    float inv = s_bc;
    #pragma unroll
    for (int i = 0; i < 12; i++) p[t + i*256] = x[i] * inv;
}

// ---------------- cat = [attn (h,l,d -> l,h*D+d) | gelu(mlp_in)] ------------
__global__ void pack_cat_kernel() {
    size_t idx = (size_t)blockIdx.x * blockDim.x + threadIdx.x;
    if (idx >= (size_t)LEN * N2) return;
    int l = (int)(idx / N2);
    int c = (int)(idx % N2);
    float val;
    if (c < HID) {
        int h = c / HD, d = c % HD;
        val = g_attn[((size_t)h * LEN + l) * HD + d];
    } else {
        float xx = g_proj[(size_t)l * N1 + 3*HID + (c - HID)];
        float inner = 0.7978845608028654f * (xx + 0.044715f * xx * xx * xx);
        val = 0.5f * xx * (1.f + tanhf(inner));
    }
    g_cat[idx] = val;
}

// ---------------- final: out = x + gate * (y)  (y already has bias) --------
__global__ void final_kernel(const float* __restrict__ x, float* __restrict__ out) {
    size_t idx = (size_t)blockIdx.x * blockDim.x + threadIdx.x;
    if (idx >= (size_t)LEN * HID) return;
    int col = (int)(idx % HID);
    out[idx] = x[idx] + g_mod[2*HID + col] * out[idx];
}

// ---------------- launcher --------------------------------------------------
extern "C" void kernel_launch(void* const* d_in, const int* in_sizes, int n_in,
                              void* d_out, int out_size) {
    const float* x       = (const float*)d_in[0];
    const float* vec     = (const float*)d_in[1];
    const float* pe      = (const float*)d_in[2];
    const float* mod_w   = (const float*)d_in[3];
    const float* mod_b   = (const float*)d_in[4];
    const float* lin1_w  = (const float*)d_in[5];
    const float* lin1_b  = (const float*)d_in[6];
    const float* lin2_w  = (const float*)d_in[7];
    const float* lin2_b  = (const float*)d_in[8];
    const float* q_scale = (const float*)d_in[9];
    const float* k_scale = (const float*)d_in[10];
    float* out = (float*)d_out;

    void *p_xmod, *p_proj, *p_q, *p_k, *p_v, *p_S, *p_attn, *p_cat;
    cudaGetSymbolAddress(&p_xmod, g_xmod);
    cudaGetSymbolAddress(&p_proj, g_proj);
    cudaGetSymbolAddress(&p_q, g_q);
    cudaGetSymbolAddress(&p_k, g_k);
    cudaGetSymbolAddress(&p_v, g_v);
    cudaGetSymbolAddress(&p_S, g_S);
    cudaGetSymbolAddress(&p_attn, g_attn);
    cudaGetSymbolAddress(&p_cat, g_cat);

    // 1) silu(vec)
    silu_kernel<<<(HID + 255)/256, 256>>>(vec);
    // 2) mod = silu(vec) @ mod_w.T + mod_b
    gemv_mod_kernel<<<(3*HID)/8, 256>>>(mod_w, mod_b);
    // 3) LN + modulation
    layernorm_kernel<<<LEN, 256>>>(x);
    // 4) proj = x_mod @ lin1_w.T + lin1_b    (3072 x 21504 x 3072, NT)
    gemm_kernel<1><<<dim3(N1/128, LEN/128, 1), 256>>>(
        (const float*)p_xmod, lin1_w, lin1_b, (float*)p_proj,
        LEN, N1, HID, 1.f, 0, 0, 0);
    // 5) qkv split + RMS + RoPE
    qkv_prep_kernel<<<(NH*LEN)/8, 256>>>(pe, q_scale, k_scale);
    // 6) logits = q @ k.T / sqrt(D)          (per head, NT, K=128)
    gemm_kernel<1><<<dim3(LEN/128, LEN/128, NH), 256>>>(
        (const float*)p_q, (const float*)p_k, nullptr, (float*)p_S,
        LEN, LEN, HD, 0.08838834764831845f,
        (size_t)LEN*HD, (size_t)LEN*HD, (size_t)LEN*LEN);
    // 7) softmax rows
    softmax_kernel<<<NH*LEN, 256>>>();
    // 8) attn = P @ V                        (per head, NN, N=128)
    gemm_kernel<0><<<dim3(1, LEN/128, NH), 256>>>(
        (const float*)p_S, (const float*)p_v, nullptr, (float*)p_attn,
        LEN, HD, LEN, 1.f,
        (size_t)LEN*LEN, (size_t)LEN*HD, (size_t)LEN*HD);
    // 9) cat = [attn | gelu(mlp_in)]
    {
        size_t tot = (size_t)LEN * N2;
        pack_cat_kernel<<<(unsigned)((tot + 255)/256), 256>>>();
    }
    // 10) y = cat @ lin2_w.T + lin2_b -> d_out  (3072 x 3072 x 15360, NT)
    gemm_kernel<1><<<dim3(HID/128, LEN/128, 1), 256>>>(
        (const float*)p_cat, lin2_w, lin2_b, out,
        LEN, HID, N2, 1.f, 0, 0, 0);
    // 11) out = x + gate * y
    {
        size_t tot = (size_t)LEN * HID;
        final_kernel<<<(unsigned)((tot + 255)/256), 256>>>(x, out);
    }
}